// round 1
// baseline (speedup 1.0000x reference)
#include <cuda_runtime.h>
#include <cstdint>
#include <cstddef>

#define C_IN    256
#define C_OUT   256
#define FANOUT  8
#define BM      64
#define BK      32
#define NTHREADS 256

// Scratch: target occupancy flags (max n_up = 400000; give headroom).
__device__ unsigned char g_target[1 << 20];
__device__ int g_is32;

// ---------------------------------------------------------------------------
// Detect whether target_idx is int64 or int32. JAX without x64 silently
// downcasts jnp.int64 -> int32. If the buffer is int32, reading pairs as
// int64 yields values >= 2^32 (hi word = next index, ~never 0) -> flag.
// ---------------------------------------------------------------------------
__global__ void detect_kernel(const long long* __restrict__ idx, int n, long long n_up) {
    if (blockIdx.x == 0 && threadIdx.x == 0) {
        int bad = 0;
        int m = (n < 64) ? n : 64;
        for (int i = 0; i < m; i++) {
            long long v = idx[i];
            if (v < 0 || v >= n_up) bad = 1;
        }
        g_is32 = bad;
    }
}

__global__ void zero_kernel(int n_up, float* __restrict__ out_tgt) {
    int i = blockIdx.x * blockDim.x + threadIdx.x;
    if (i < n_up) {
        g_target[i] = 0;
        if (out_tgt) out_tgt[i] = 0.0f;
    }
}

__global__ void scatter_kernel(const void* __restrict__ idxp, int n,
                               float* __restrict__ out_tgt) {
    int i = blockIdx.x * blockDim.x + threadIdx.x;
    if (i >= n) return;
    long long v = g_is32 ? (long long)((const int*)idxp)[i]
                         : ((const long long*)idxp)[i];
    g_target[v] = 1;
    if (out_tgt) out_tgt[v] = 1.0f;
}

// ---------------------------------------------------------------------------
// Fused kernel: one CTA computes a 64x256 tile of fea_up for a fixed fanout
// slot k, then in the epilogue computes exist (warp butterfly over the 256
// columns), applies keep = exist>0 | target, and writes the masked rows,
// exist values, all in one pass.
//
// Thread layout: tid = ty*32 + tx; thread owns rows [ty*8, ty*8+8) and
// columns {tx*4..tx*4+3} U {128+tx*4..128+tx*4+3}  (split mapping ->
// conflict-free LDS.128 on B and fully coalesced STG.128 on output).
// All 32 lanes of a warp share the same 8 rows -> exist reduction is a
// pure warp shuffle butterfly.
// ---------------------------------------------------------------------------
__global__ __launch_bounds__(NTHREADS, 2)
void fused_up_kernel(const float* __restrict__ fea,
                     const float* __restrict__ W_up,
                     const float* __restrict__ b_up,
                     const float* __restrict__ W_cls,
                     const float* __restrict__ b_cls,
                     float* __restrict__ out_pruned,
                     float* __restrict__ out_exist,
                     int n_parent)
{
    __shared__ float As[BK][BM];      // A transposed: As[kk][row]
    __shared__ float Bs[BK][C_OUT];   // B row-major:  Bs[kk][col]

    const int k   = blockIdx.y;
    const int n0  = blockIdx.x * BM;
    const int tid = threadIdx.x;
    const int ty  = tid >> 5;   // 0..7  (row group)
    const int tx  = tid & 31;   // 0..31 (col group / lane)
    const float* W = W_up + (size_t)k * C_IN * C_OUT;

    float acc[8][8];
    #pragma unroll
    for (int i = 0; i < 8; i++)
        #pragma unroll
        for (int j = 0; j < 8; j++)
            acc[i][j] = 0.0f;

    for (int kk0 = 0; kk0 < C_IN; kk0 += BK) {
        // ---- load A tile: 64 rows x 32 cols, transposed into smem ----
        #pragma unroll
        for (int t = tid; t < (BM * BK) / 4; t += NTHREADS) {
            int row = t >> 3;      // 8 float4s per row
            int c4  = t & 7;
            int gn  = n0 + row;
            float4 v = make_float4(0.f, 0.f, 0.f, 0.f);
            if (gn < n_parent)
                v = *(const float4*)&fea[(size_t)gn * C_IN + kk0 + c4 * 4];
            As[c4 * 4 + 0][row] = v.x;
            As[c4 * 4 + 1][row] = v.y;
            As[c4 * 4 + 2][row] = v.z;
            As[c4 * 4 + 3][row] = v.w;
        }
        // ---- load B tile: 32 rows x 256 cols ----
        #pragma unroll
        for (int t = tid; t < (BK * C_OUT) / 4; t += NTHREADS) {
            int row = t >> 6;      // 64 float4s per row
            int c4  = t & 63;
            *(float4*)&Bs[row][c4 * 4] =
                *(const float4*)&W[(size_t)(kk0 + row) * C_OUT + c4 * 4];
        }
        __syncthreads();

        #pragma unroll
        for (int kk = 0; kk < BK; kk++) {
            float4 a0 = *(const float4*)&As[kk][ty * 8];
            float4 a1 = *(const float4*)&As[kk][ty * 8 + 4];
            float4 b0 = *(const float4*)&Bs[kk][tx * 4];
            float4 b1 = *(const float4*)&Bs[kk][128 + tx * 4];
            float a[8] = {a0.x, a0.y, a0.z, a0.w, a1.x, a1.y, a1.z, a1.w};
            float b[8] = {b0.x, b0.y, b0.z, b0.w, b1.x, b1.y, b1.z, b1.w};
            #pragma unroll
            for (int i = 0; i < 8; i++)
                #pragma unroll
                for (int j = 0; j < 8; j++)
                    acc[i][j] = fmaf(a[i], b[j], acc[i][j]);
        }
        __syncthreads();
    }

    // ---- epilogue: bias, exist dot + warp reduce, keep mask, stores ----
    float4 bu0 = *(const float4*)&b_up[tx * 4];
    float4 bu1 = *(const float4*)&b_up[128 + tx * 4];
    float4 wc0 = *(const float4*)&W_cls[tx * 4];
    float4 wc1 = *(const float4*)&W_cls[128 + tx * 4];
    float bu[8] = {bu0.x, bu0.y, bu0.z, bu0.w, bu1.x, bu1.y, bu1.z, bu1.w};
    float wc[8] = {wc0.x, wc0.y, wc0.z, wc0.w, wc1.x, wc1.y, wc1.z, wc1.w};
    const float bc = b_cls[0];

    float ex[8];
    #pragma unroll
    for (int i = 0; i < 8; i++) {
        float s = 0.0f;
        #pragma unroll
        for (int j = 0; j < 8; j++) {
            acc[i][j] += bu[j];
            s = fmaf(acc[i][j], wc[j], s);
        }
        #pragma unroll
        for (int off = 16; off; off >>= 1)
            s += __shfl_xor_sync(0xFFFFFFFFu, s, off);
        ex[i] = s + bc;   // full exist for row ty*8+i, in every lane
    }

    #pragma unroll
    for (int i = 0; i < 8; i++) {
        int n = n0 + ty * 8 + i;
        if (n >= n_parent) continue;
        size_t m = (size_t)n * FANOUT + k;   // row in fea_up / exist / target
        bool keep = (ex[i] > 0.0f) || (g_target[m] != 0);
        if (out_exist && tx == 0) out_exist[m] = ex[i];
        float4 o0, o1;
        if (keep) {
            o0 = make_float4(acc[i][0], acc[i][1], acc[i][2], acc[i][3]);
            o1 = make_float4(acc[i][4], acc[i][5], acc[i][6], acc[i][7]);
        } else {
            o0 = make_float4(0.f, 0.f, 0.f, 0.f);
            o1 = o0;
        }
        float* orow = out_pruned + m * (size_t)C_OUT;
        *(float4*)&orow[tx * 4]       = o0;
        *(float4*)&orow[128 + tx * 4] = o1;
    }
}

// ---------------------------------------------------------------------------
// Inputs (metadata order): fea [N,256] f32, W_up [8,256,256] f32, b_up [256],
// W_cls [256,1], b_cls [1], target_idx [200000] i64 (or i32 if JAX downcast).
// Output assumed: concat([fea_pruned (n_up*256), exist (n_up), target (n_up)])
// as float32; degrade gracefully if out_size indicates fewer outputs.
// ---------------------------------------------------------------------------
extern "C" void kernel_launch(void* const* d_in, const int* in_sizes, int n_in,
                              void* d_out, int out_size) {
    const float* fea   = (const float*)d_in[0];
    const float* W_up  = (const float*)d_in[1];
    const float* b_up  = (const float*)d_in[2];
    const float* W_cls = (const float*)d_in[3];
    const float* b_cls = (const float*)d_in[4];
    const void*  tidx  = d_in[5];

    const int n_parent = in_sizes[0] / C_IN;
    const int n_tgt    = in_sizes[5];
    const int n_up     = n_parent * FANOUT;

    float* out        = (float*)d_out;
    float* out_pruned = out;
    float* out_exist  = nullptr;
    float* out_tgt    = nullptr;
    long long need_exist  = (long long)n_up * (C_OUT + 1);
    long long need_target = (long long)n_up * (C_OUT + 2);
    if ((long long)out_size >= need_exist)
        out_exist = out + (size_t)n_up * C_OUT;
    if ((long long)out_size >= need_target)
        out_tgt = out + (size_t)n_up * (C_OUT + 1);

    detect_kernel<<<1, 32>>>((const long long*)tidx, n_tgt, (long long)n_up);
    zero_kernel<<<(n_up + 255) / 256, 256>>>(n_up, out_tgt);
    scatter_kernel<<<(n_tgt + 255) / 256, 256>>>(tidx, n_tgt, out_tgt);

    dim3 grid((n_parent + BM - 1) / BM, FANOUT);
    fused_up_kernel<<<grid, NTHREADS>>>(fea, W_up, b_up, W_cls, b_cls,
                                        out_pruned, out_exist, n_parent);
}

// round 3
// speedup vs baseline: 2.1873x; 2.1873x over previous
#include <cuda_runtime.h>
#include <cstdint>
#include <cstddef>

#define C_IN    256
#define C_OUT   256
#define FANOUT  8
#define BM      128
#define BN      128
#define BK      16
#define NITER   (C_IN / BK)        // 16
#define STAGES  4

// smem geometry (bytes)
#define A_ROW_F   20               // 16 + 4 pad floats
#define B_ROW_F   136              // 128 + 8 pad floats
#define A_STAGE_B (BM * A_ROW_F * 4)          // 10240
#define B_STAGE_B (BK * B_ROW_F * 4)          // 8704
#define STAGE_B   (A_STAGE_B + B_STAGE_B)     // 18944
#define STAG_ROW_F 132             // epilogue staging row stride (floats)
#define SMEM_TOTAL (STAGES * STAGE_B)         // 75776  (>= 128*132*4 = 67584)

// ---------------- device scratch -------------------------------------------
__device__ float         g_weff[FANOUT * C_IN];
__device__ float         g_c0;
__device__ unsigned char g_target[1 << 20];
__device__ unsigned char g_keep[1 << 20];
__device__ int           g_is32;

// ---------------- helpers ---------------------------------------------------
__device__ __forceinline__ uint32_t smem_u32(const void* p) {
    uint32_t a;
    asm("{ .reg .u64 t; cvta.to.shared.u64 t, %1; cvt.u32.u64 %0, t; }" : "=r"(a) : "l"(p));
    return a;
}
__device__ __forceinline__ void cp16(uint32_t dst, const void* src, uint32_t sz) {
    asm volatile("cp.async.cg.shared.global [%0], [%1], 16, %2;"
                 :: "r"(dst), "l"((unsigned long long)__cvta_generic_to_global(src)), "r"(sz)
                 : "memory");
}
__device__ __forceinline__ void cp_commit() { asm volatile("cp.async.commit_group;" ::: "memory"); }
__device__ __forceinline__ void cp_wait3()  { asm volatile("cp.async.wait_group 3;" ::: "memory"); }
__device__ __forceinline__ uint32_t to_tf32(float f) {
    uint32_t r;
    asm("cvt.rna.tf32.f32 %0, %1;" : "=r"(r) : "f"(f));
    return r;
}
__device__ __forceinline__ void mma_tf32(float& c0, float& c1, float& c2, float& c3,
                                         uint32_t a0, uint32_t a1, uint32_t a2, uint32_t a3,
                                         uint32_t b0, uint32_t b1) {
    asm volatile("mma.sync.aligned.m16n8k8.row.col.f32.tf32.tf32.f32 "
                 "{%0,%1,%2,%3}, {%4,%5,%6,%7}, {%8,%9}, {%0,%1,%2,%3};"
                 : "+f"(c0), "+f"(c1), "+f"(c2), "+f"(c3)
                 : "r"(a0), "r"(a1), "r"(a2), "r"(a3), "r"(b0), "r"(b1));
}

// ---------------- small kernels --------------------------------------------
__global__ void detect_kernel(const long long* __restrict__ idx, int n, long long n_up) {
    if (threadIdx.x == 0) {
        int bad = 0;
        int m = (n < 64) ? n : 64;
        for (int i = 0; i < m; i++) {
            long long v = idx[i];
            if (v < 0 || v >= n_up) bad = 1;
        }
        g_is32 = bad;
    }
}
__global__ void zero_kernel(int n_up, float* __restrict__ out_tgt) {
    int i = blockIdx.x * blockDim.x + threadIdx.x;
    if (i < n_up) {
        g_target[i] = 0;
        if (out_tgt) out_tgt[i] = 0.0f;
    }
}
__global__ void scatter_kernel(const void* __restrict__ idxp, int n, float* __restrict__ out_tgt) {
    int i = blockIdx.x * blockDim.x + threadIdx.x;
    if (i >= n) return;
    long long v = g_is32 ? (long long)((const int*)idxp)[i] : ((const long long*)idxp)[i];
    g_target[v] = 1;
    if (out_tgt) out_tgt[v] = 1.0f;
}
__global__ void weff_kernel(const float* __restrict__ W_up, const float* __restrict__ W_cls,
                            const float* __restrict__ b_up, const float* __restrict__ b_cls) {
    __shared__ float wc[C_OUT];
    int k = blockIdx.x, c = threadIdx.x;
    wc[c] = W_cls[c];
    __syncthreads();
    const float* row = W_up + k * 65536 + c * 256;
    float s = 0.0f;
    #pragma unroll 8
    for (int d = 0; d < C_OUT; d++) s = fmaf(row[d], wc[d], s);
    g_weff[k * 256 + c] = s;
    if (k == 0 && c == 0) {
        float s2 = 0.0f;
        for (int d = 0; d < C_OUT; d++) s2 = fmaf(b_up[d], wc[d], s2);
        g_c0 = s2 + b_cls[0];
    }
}
// fp32 exist + keep (exact sign decisions): one warp per parent row
__global__ void exist_kernel(const float* __restrict__ fea, float* __restrict__ out_exist,
                             int n_parent) {
    __shared__ float ws[FANOUT * C_IN];
    int tid = threadIdx.x;
    for (int i = tid; i < FANOUT * C_IN; i += 256) ws[i] = g_weff[i];
    __syncthreads();
    int w = tid >> 5, lane = tid & 31;
    int n = blockIdx.x * 8 + w;
    if (n >= n_parent) return;
    float f[8];
    #pragma unroll
    for (int i = 0; i < 8; i++) f[i] = fea[(size_t)n * 256 + lane + 32 * i];
    float acc[8];
    #pragma unroll
    for (int k = 0; k < 8; k++) acc[k] = 0.0f;
    #pragma unroll
    for (int k = 0; k < 8; k++)
        #pragma unroll
        for (int i = 0; i < 8; i++)
            acc[k] = fmaf(f[i], ws[k * 256 + lane + 32 * i], acc[k]);
    #pragma unroll
    for (int k = 0; k < 8; k++)
        #pragma unroll
        for (int off = 16; off; off >>= 1)
            acc[k] += __shfl_xor_sync(0xFFFFFFFFu, acc[k], off);
    if (lane == 0) {
        size_t m = (size_t)n * 8;
        float c0 = g_c0;
        #pragma unroll
        for (int k = 0; k < 8; k++) {
            float e = acc[k] + c0;
            g_keep[m + k] = ((e > 0.0f) || (g_target[m + k] != 0)) ? 1 : 0;
            if (out_exist) out_exist[m + k] = e;
        }
    }
}

// ---------------- main GEMM: tf32 mma.sync, 4-stage cp.async ----------------
__device__ __forceinline__ void load_stage(char* sm, const float* __restrict__ fea,
                                           const float* __restrict__ Wk,
                                           int n0, int nb, int kc0, int tid, int n_parent) {
    // A: 128 rows x 16 floats  -> 512 cp16
    #pragma unroll
    for (int h = 0; h < 2; h++) {
        int c = tid + 256 * h;
        int row = c >> 2, kp = c & 3;
        int n = n0 + row;
        uint32_t dst = smem_u32(sm + row * (A_ROW_F * 4) + kp * 16);
        const float* src = (n < n_parent) ? (fea + (size_t)n * C_IN + kc0 + kp * 4) : fea;
        cp16(dst, src, (n < n_parent) ? 16u : 0u);
    }
    // B: 16 rows x 128 floats -> 512 cp16  (W_up[k] is already K-major)
    #pragma unroll
    for (int h = 0; h < 2; h++) {
        int c = tid + 256 * h;
        int row = c >> 5, p = c & 31;
        uint32_t dst = smem_u32(sm + A_STAGE_B + row * (B_ROW_F * 4) + p * 16);
        cp16(dst, Wk + (size_t)(kc0 + row) * C_OUT + nb + p * 4, 16u);
    }
}

__global__ __launch_bounds__(256, 2)
void gemm_tf32_kernel(const float* __restrict__ fea, const float* __restrict__ W_up,
                      const float* __restrict__ b_up, float* __restrict__ out,
                      int n_parent) {
    extern __shared__ char smem[];
    const int tid  = threadIdx.x;
    const int wid  = tid >> 5;
    const int lane = tid & 31;
    const int grp  = lane >> 2;     // 0..7
    const int tig  = lane & 3;      // 0..3
    const int wm   = wid >> 2;      // 0..1  (M half)
    const int wn   = wid & 3;       // 0..3  (N quarter)

    const int n0 = blockIdx.x * BM;
    const int nb = blockIdx.y * BN;
    const int kf = blockIdx.z;
    const float* Wk = W_up + (size_t)kf * C_IN * C_OUT;

    float acc[4][4][4];
    #pragma unroll
    for (int mi = 0; mi < 4; mi++)
        #pragma unroll
        for (int ni = 0; ni < 4; ni++)
            #pragma unroll
            for (int r = 0; r < 4; r++)
                acc[mi][ni][r] = 0.0f;

    // prologue: stages 0..2
    #pragma unroll
    for (int s = 0; s < 3; s++) {
        load_stage(smem + s * STAGE_B, fea, Wk, n0, nb, s * BK, tid, n_parent);
        cp_commit();
    }

    for (int it = 0; it < NITER; it++) {
        if (it < NITER - 3)
            load_stage(smem + ((it + 3) & 3) * STAGE_B, fea, Wk, n0, nb,
                       (it + 3) * BK, tid, n_parent);
        cp_commit();
        cp_wait3();
        __syncthreads();

        const float* As = (const float*)(smem + (it & 3) * STAGE_B);
        const float* Bs = (const float*)(smem + (it & 3) * STAGE_B + A_STAGE_B);

        #pragma unroll
        for (int ks = 0; ks < 2; ks++) {
            const int kc = ks * 8;
            uint32_t a[4][4];
            #pragma unroll
            for (int mi = 0; mi < 4; mi++) {
                int r0 = wm * 64 + mi * 16 + grp;
                a[mi][0] = to_tf32(As[r0 * A_ROW_F + kc + tig]);
                a[mi][1] = to_tf32(As[(r0 + 8) * A_ROW_F + kc + tig]);
                a[mi][2] = to_tf32(As[r0 * A_ROW_F + kc + tig + 4]);
                a[mi][3] = to_tf32(As[(r0 + 8) * A_ROW_F + kc + tig + 4]);
            }
            uint32_t b[4][2];
            #pragma unroll
            for (int ni = 0; ni < 4; ni++) {
                int col = wn * 32 + ni * 8 + grp;
                b[ni][0] = to_tf32(Bs[(kc + tig) * B_ROW_F + col]);
                b[ni][1] = to_tf32(Bs[(kc + tig + 4) * B_ROW_F + col]);
            }
            #pragma unroll
            for (int mi = 0; mi < 4; mi++)
                #pragma unroll
                for (int ni = 0; ni < 4; ni++)
                    mma_tf32(acc[mi][ni][0], acc[mi][ni][1], acc[mi][ni][2], acc[mi][ni][3],
                             a[mi][0], a[mi][1], a[mi][2], a[mi][3],
                             b[ni][0], b[ni][1]);
        }
        __syncthreads();   // protect stage (it&3) from next iteration's cp.async
    }

    // ---------------- epilogue: stage C through smem, fused bias+mask ------
    float* stag = (float*)smem;
    #pragma unroll
    for (int mi = 0; mi < 4; mi++) {
        int r0 = wm * 64 + mi * 16 + grp;
        #pragma unroll
        for (int ni = 0; ni < 4; ni++) {
            int c0 = wn * 32 + ni * 8 + 2 * tig;
            *(float2*)&stag[r0 * STAG_ROW_F + c0]       = make_float2(acc[mi][ni][0], acc[mi][ni][1]);
            *(float2*)&stag[(r0 + 8) * STAG_ROW_F + c0] = make_float2(acc[mi][ni][2], acc[mi][ni][3]);
        }
    }
    __syncthreads();

    #pragma unroll
    for (int j = 0; j < 16; j++) {
        int idx = j * 256 + tid;            // 0..4095 float4 units
        int row = idx >> 5;
        int c4  = (idx & 31) * 4;
        int n = n0 + row;
        if (n < n_parent) {
            size_t m = (size_t)n * FANOUT + kf;
            float4 o;
            if (g_keep[m]) {
                float4 v  = *(float4*)&stag[row * STAG_ROW_F + c4];
                float4 bb = *(const float4*)&b_up[nb + c4];
                o = make_float4(v.x + bb.x, v.y + bb.y, v.z + bb.z, v.w + bb.w);
            } else {
                o = make_float4(0.f, 0.f, 0.f, 0.f);
            }
            *(float4*)&out[m * (size_t)C_OUT + nb + c4] = o;
        }
    }
}

// ---------------- launch ----------------------------------------------------
extern "C" void kernel_launch(void* const* d_in, const int* in_sizes, int n_in,
                              void* d_out, int out_size) {
    const float* fea   = (const float*)d_in[0];
    const float* W_up  = (const float*)d_in[1];
    const float* b_up  = (const float*)d_in[2];
    const float* W_cls = (const float*)d_in[3];
    const float* b_cls = (const float*)d_in[4];
    const void*  tidx  = d_in[5];

    const int n_parent = in_sizes[0] / C_IN;
    const int n_tgt    = in_sizes[5];
    const int n_up     = n_parent * FANOUT;

    float* out        = (float*)d_out;
    float* out_exist  = nullptr;
    float* out_tgt    = nullptr;
    long long need_exist  = (long long)n_up * (C_OUT + 1);
    long long need_target = (long long)n_up * (C_OUT + 2);
    if ((long long)out_size >= need_exist)  out_exist = out + (size_t)n_up * C_OUT;
    if ((long long)out_size >= need_target) out_tgt   = out + (size_t)n_up * (C_OUT + 1);

    static int smem_set = 0;
    if (!smem_set) {
        cudaFuncSetAttribute(gemm_tf32_kernel,
                             cudaFuncAttributeMaxDynamicSharedMemorySize, SMEM_TOTAL);
        smem_set = 1;
    }

    detect_kernel<<<1, 32>>>((const long long*)tidx, n_tgt, (long long)n_up);
    zero_kernel<<<(n_up + 255) / 256, 256>>>(n_up, out_tgt);
    scatter_kernel<<<(n_tgt + 255) / 256, 256>>>(tidx, n_tgt, out_tgt);
    weff_kernel<<<FANOUT, C_OUT>>>(W_up, W_cls, b_up, b_cls);
    exist_kernel<<<(n_parent + 7) / 8, 256>>>(fea, out_exist, n_parent);

    dim3 grid((n_parent + BM - 1) / BM, C_OUT / BN, FANOUT);
    gemm_tf32_kernel<<<grid, 256, SMEM_TOTAL>>>(fea, W_up, b_up, out, n_parent);
}